// round 2
// baseline (speedup 1.0000x reference)
#include <cuda_runtime.h>
#include <cstdint>
#include <math_constants.h>

// Problem constants (fixed shapes for this problem)
#define DIM      256
#define NPIX     65536      // DIM*DIM
#define HO       128
#define NOUT     16384      // HO*HO
#define HALFOUT  8192       // outputs per half-CTA
#define NTHREADS 1024

// Staging table: for pixel p, where it lands in the scrambled smem layout.
// bit15 = half, bits[0:15) = float slot within that half (0..32767).
// gather_idx is a permutation of [0,65536), so this is well-defined.
__device__ uint16_t g_stage[NPIX];

// ---------------------------------------------------------------------------
// Pass 0: build stage table from gather_idx (int64 OR int32, autodetected).
// gather_idx is a permutation: among 8 sampled entries at most one is zero,
// so "first 8 odd u32 words all zero" <=> int64 layout.
// thread o4 = o*4 + k handles entry (o,k):
//   stage[gather_idx[o,k]] = (o>>13)<<15 | ((o & 8191)*4 + k)
// ---------------------------------------------------------------------------
__global__ void build_stage_kernel(const uint32_t* __restrict__ src) {
    bool is64 = true;
#pragma unroll
    for (int i = 0; i < 8; i++) is64 &= (src[2 * i + 1] == 0u);
    int o4 = blockIdx.x * blockDim.x + threadIdx.x;   // 0 .. 65535
    uint32_t p = is64 ? src[2 * o4] : src[o4];
    uint32_t o = (uint32_t)o4 >> 2;
    uint32_t k = (uint32_t)o4 & 3u;
    uint32_t h = o >> 13;                             // output half
    uint32_t slot = ((o & 8191u) << 2) | k;           // 0 .. 32767
    g_stage[p] = (uint16_t)((h << 15) | slot);
}

// ---------------------------------------------------------------------------
// Main kernel: 2 CTAs per plane (blockIdx.x = plane*2 + half).
// Phase 1: stream the whole plane coalesced; scatter the ~half of the pixels
//          belonging to this CTA's output-half into scrambled smem slots.
//          (adjacent bid = paired CTA reads the same plane concurrently ->
//           second read is an L2 hit, DRAM traffic stays 1x)
// Phase 2: each output's 4 candidates are CONTIGUOUS in smem -> one
//          conflict-free sequential LDS.128 per output, fmax4, coalesced STG.
// ---------------------------------------------------------------------------
extern __shared__ float sdata[];   // 32768 floats = 128 KB dynamic

__global__ void __launch_bounds__(NTHREADS, 1)
pool_kernel(const float* __restrict__ x, float* __restrict__ out) {
    const int plane = blockIdx.x >> 1;
    const unsigned h = blockIdx.x & 1u;
    const int t = threadIdx.x;

    const float4* __restrict__ xp =
        reinterpret_cast<const float4*>(x + (size_t)plane * NPIX);
    const unsigned long long* __restrict__ st =
        reinterpret_cast<const unsigned long long*>(g_stage);

    const unsigned hbit = h << 15;

    // ---- Phase 1: coalesced read + scrambled predicated scatter to smem ----
#pragma unroll
    for (int w = 0; w < 16; w++) {
        const int q = t + w * NTHREADS;         // float4 index, 0..16383
        const float4 v = xp[q];
        const unsigned long long sv = st[q];    // 4 x uint16 stage entries
        unsigned s0 = (unsigned)(sv      ) & 0xFFFFu;
        unsigned s1 = (unsigned)(sv >> 16) & 0xFFFFu;
        unsigned s2 = (unsigned)(sv >> 32) & 0xFFFFu;
        unsigned s3 = (unsigned)(sv >> 48) & 0xFFFFu;
        if ((s0 & 0x8000u) == hbit) sdata[s0 & 0x7FFFu] = v.x;
        if ((s1 & 0x8000u) == hbit) sdata[s1 & 0x7FFFu] = v.y;
        if ((s2 & 0x8000u) == hbit) sdata[s2 & 0x7FFFu] = v.z;
        if ((s3 & 0x8000u) == hbit) sdata[s3 & 0x7FFFu] = v.w;
    }
    __syncthreads();

    // ---- Phase 2: sequential LDS.128 gather + max + coalesced store ----
    float* __restrict__ op = out + (size_t)plane * NOUT + h * HALFOUT;
    const float4* __restrict__ sg = reinterpret_cast<const float4*>(sdata);
#pragma unroll
    for (int k = 0; k < HALFOUT / NTHREADS; k++) {   // 8 outputs / thread
        const int o = t + k * NTHREADS;
        const float4 g = sg[o];
        op[o] = fmaxf(fmaxf(g.x, g.y), fmaxf(g.z, g.w));
    }
}

// ---------------------------------------------------------------------------
// Launch
// ---------------------------------------------------------------------------
extern "C" void kernel_launch(void* const* d_in, const int* in_sizes, int n_in,
                              void* d_out, int out_size) {
    const float*    x    = (const float*)d_in[0];
    const uint32_t* gidx = (const uint32_t*)d_in[1];
    float*          out  = (float*)d_out;

    const int planes = in_sizes[0] / NPIX;   // 16*64 = 1024

    // Immediate (non-stream) API, idempotent -> capture-safe.
    cudaFuncSetAttribute(pool_kernel,
                         cudaFuncAttributeMaxDynamicSharedMemorySize,
                         32768 * (int)sizeof(float));

    build_stage_kernel<<<NPIX / 256, 256>>>(gidx);
    pool_kernel<<<planes * 2, NTHREADS, 32768 * sizeof(float)>>>(x, out);
}